// round 6
// baseline (speedup 1.0000x reference)
#include <cuda_runtime.h>
#include <cuda_fp16.h>

#define NUM_NODES 100000
#define EMB_DIM   64
#define NUM_EDGES 1280000
#define TILE      1024
#define NUM_TILES ((NUM_NODES + TILE - 1) / TILE)   // 98

// ---- scratch (static device globals; no allocation allowed) ----
// All propagated states stored as y = dinv * x, fp16, 32 uints per node row.
__device__ __align__(16) unsigned g_E[NUM_NODES * 32];  // y0 = dinv*emb
__device__ __align__(16) unsigned g_A[NUM_NODES * 32];  // y1
__device__ __align__(16) unsigned g_B[NUM_NODES * 32];  // y2
__device__ float g_dinv[NUM_NODES];
__device__ int   g_deg[NUM_NODES];
__device__ int   g_row[NUM_NODES];      // CSR offsets (bumped in place by fill)
__device__ int   g_tile[NUM_TILES];
__device__ int   g_tpfx[NUM_TILES];
__device__ int   g_csrc[NUM_EDGES];     // CSR: src per slot (no weight needed!)

__global__ void init_kernel() {
    int i = blockIdx.x * blockDim.x + threadIdx.x;
    if (i < NUM_NODES) g_deg[i] = 0;
}

__global__ void deg_kernel(const int* __restrict__ dst) {
    int e = blockIdx.x * blockDim.x + threadIdx.x;
    if (e < NUM_EDGES) atomicAdd(&g_deg[dst[e]], 1);
}

// per-tile exclusive scan of deg -> g_row (warp-shuffle), also emit dinv
__global__ void scan_tiles() {
    __shared__ int wsum[32];
    int i = blockIdx.x * TILE + threadIdx.x;
    int lane = threadIdx.x & 31;
    int wid  = threadIdx.x >> 5;
    int v = (i < NUM_NODES) ? g_deg[i] : 0;
    if (i < NUM_NODES) g_dinv[i] = (v > 0) ? rsqrtf((float)v) : 0.0f;

    int x = v;                               // warp inclusive scan
    #pragma unroll
    for (int off = 1; off < 32; off <<= 1) {
        int t = __shfl_up_sync(0xffffffffu, x, off);
        if (lane >= off) x += t;
    }
    if (lane == 31) wsum[wid] = x;
    __syncthreads();
    if (wid == 0) {                          // scan the 32 warp totals
        int y = wsum[lane];
        #pragma unroll
        for (int off = 1; off < 32; off <<= 1) {
            int t = __shfl_up_sync(0xffffffffu, y, off);
            if (lane >= off) y += t;
        }
        wsum[lane] = y;                      // inclusive
    }
    __syncthreads();
    int base = (wid > 0) ? wsum[wid - 1] : 0;
    if (i < NUM_NODES) g_row[i] = base + x - v;   // exclusive within tile
    if (threadIdx.x == TILE - 1) g_tile[blockIdx.x] = wsum[31];
}

__global__ void scan_tilesums() {            // 1 block, 128 threads, shuffle scan
    __shared__ int wsum[4];
    int t = threadIdx.x;
    int lane = t & 31, wid = t >> 5;
    int v = (t < NUM_TILES) ? g_tile[t] : 0;
    int x = v;
    #pragma unroll
    for (int off = 1; off < 32; off <<= 1) {
        int a = __shfl_up_sync(0xffffffffu, x, off);
        if (lane >= off) x += a;
    }
    if (lane == 31) wsum[wid] = x;
    __syncthreads();
    int base = 0;
    for (int k = 0; k < wid; k++) base += wsum[k];
    if (t < NUM_TILES) g_tpfx[t] = base + x - v;   // exclusive
}

__global__ void scan_apply() {
    int i = blockIdx.x * blockDim.x + threadIdx.x;
    if (i < NUM_NODES) g_row[i] += g_tpfx[i / TILE];
}

// bucket edges by dst, bumping g_row in place (after: g_row[d] == row end)
__global__ void fill_kernel(const int* __restrict__ src, const int* __restrict__ dst) {
    int e = blockIdx.x * blockDim.x + threadIdx.x;
    if (e >= NUM_EDGES) return;
    int pos = atomicAdd(&g_row[dst[e]], 1);
    g_csrc[pos] = src[e];
}

// E = fp16(dinv[node] * emb) — runs after dinv is ready
__global__ void convert_kernel(const float4* __restrict__ emb4) {
    int i = blockIdx.x * blockDim.x + threadIdx.x;
    if (i >= NUM_NODES * 16) return;         // float4 chunks
    float dv = __ldg(&g_dinv[i >> 4]);
    float4 v = __ldg(&emb4[i]);
    __half2 lo = __floats2half2_rn(v.x * dv, v.y * dv);
    __half2 hi = __floats2half2_rn(v.z * dv, v.w * dv);
    uint2 p;
    p.x = *reinterpret_cast<unsigned*>(&lo);
    p.y = *reinterpret_cast<unsigned*>(&hi);
    reinterpret_cast<uint2*>(g_E)[i] = p;
}

__device__ __forceinline__ float2 h2f(unsigned u) {
    __half2 h = *reinterpret_cast<__half2*>(&u);
    return __half22float2(h);
}

// Warp-per-node pull in y-space: sum = Σ_{s∈N(g)} y_in[s]   (no per-edge weight)
//   layer 0: E -> A:  y1 = sum / deg
//   layer 1: A -> B:  y2 = sum / deg
//   layer 2: B -> out: out = (emb + sqrt(deg)*(y1+y2) + dinv*sum) * 0.25
__global__ void __launch_bounds__(256) pull_kernel(const float2* __restrict__ emb2,
                                                   float2* __restrict__ out2,
                                                   int layer) {
    int g = (blockIdx.x * blockDim.x + threadIdx.x) >> 5;   // dst node
    int lane = threadIdx.x & 31;                            // uint lane (2 halves)
    if (g >= NUM_NODES) return;

    const unsigned* xin;
    if (layer == 0)      xin = g_E;
    else if (layer == 1) xin = g_A;
    else                 xin = g_B;

    int beg = (g == 0) ? 0 : __ldg(&g_row[g - 1]);
    int end = __ldg(&g_row[g]);

    float ax = 0.f, ay = 0.f;
    int e = beg;
    for (; e + 4 <= end; e += 4) {           // 4-way unroll: MLP vs L2 latency
        int s0 = __ldg(&g_csrc[e]);
        int s1 = __ldg(&g_csrc[e + 1]);
        int s2 = __ldg(&g_csrc[e + 2]);
        int s3 = __ldg(&g_csrc[e + 3]);
        unsigned v0 = __ldg(&xin[s0 * 32 + lane]);
        unsigned v1 = __ldg(&xin[s1 * 32 + lane]);
        unsigned v2 = __ldg(&xin[s2 * 32 + lane]);
        unsigned v3 = __ldg(&xin[s3 * 32 + lane]);
        float2 f0 = h2f(v0), f1 = h2f(v1), f2 = h2f(v2), f3 = h2f(v3);
        ax += f0.x + f1.x + f2.x + f3.x;
        ay += f0.y + f1.y + f2.y + f3.y;
    }
    for (; e < end; e++) {
        int s0 = __ldg(&g_csrc[e]);
        float2 f0 = h2f(__ldg(&xin[s0 * 32 + lane]));
        ax += f0.x;
        ay += f0.y;
    }

    if (layer < 2) {
        float dv = __ldg(&g_dinv[g]);
        float inv_deg = dv * dv;             // 1/deg (0 if deg==0)
        __half2 h = __floats2half2_rn(ax * inv_deg, ay * inv_deg);
        unsigned* xout = (layer == 0) ? g_A : g_B;
        xout[g * 32 + lane] = *reinterpret_cast<unsigned*>(&h);
    } else {
        float dv = __ldg(&g_dinv[g]);
        float sq = sqrtf((float)__ldg(&g_deg[g]));   // sqrt(deg), 0 if deg==0
        int idx = g * 32 + lane;
        float2 em = __ldg(&emb2[idx]);
        float2 y1 = h2f(g_A[idx]);
        float2 y2 = h2f(g_B[idx]);
        float2 r;
        r.x = (em.x + sq * (y1.x + y2.x) + dv * ax) * 0.25f;
        r.y = (em.y + sq * (y1.y + y2.y) + dv * ay) * 0.25f;
        out2[idx] = r;
    }
}

extern "C" void kernel_launch(void* const* d_in, const int* in_sizes, int n_in,
                              void* d_out, int out_size) {
    const int*   edge = (const int*)d_in[0];   // [2, NUM_EDGES]
    const float* emb  = (const float*)d_in[1]; // [NUM_NODES, EMB_DIM]
    const int* src = edge;
    const int* dst = edge + NUM_EDGES;
    const float4* emb4 = (const float4*)emb;
    const float2* emb2 = (const float2*)emb;
    float2* out2 = (float2*)d_out;

    const int TPB = 256;

    init_kernel<<<(NUM_NODES + TPB - 1) / TPB, TPB>>>();
    deg_kernel<<<(NUM_EDGES + TPB - 1) / TPB, TPB>>>(dst);

    scan_tiles<<<NUM_TILES, TILE>>>();
    scan_tilesums<<<1, 128>>>();
    scan_apply<<<(NUM_NODES + TPB - 1) / TPB, TPB>>>();

    convert_kernel<<<(NUM_NODES * 16 + TPB - 1) / TPB, TPB>>>(emb4);
    fill_kernel<<<(NUM_EDGES + TPB - 1) / TPB, TPB>>>(src, dst);

    const int warps_per_block = TPB / 32;    // 8 nodes per block
    const int pull_blocks = (NUM_NODES + warps_per_block - 1) / warps_per_block;

    pull_kernel<<<pull_blocks, TPB>>>(emb2, out2, 0);  // E -> A
    pull_kernel<<<pull_blocks, TPB>>>(emb2, out2, 1);  // A -> B
    pull_kernel<<<pull_blocks, TPB>>>(emb2, out2, 2);  // B -> out (fused)
}

// round 7
// speedup vs baseline: 1.6244x; 1.6244x over previous
#include <cuda_runtime.h>
#include <cuda_fp16.h>

#define NUM_NODES 100000
#define EMB_DIM   64
#define NUM_EDGES 1280000
#define TILE      1024
#define NUM_TILES ((NUM_NODES + TILE - 1) / TILE)   // 98

// ---- scratch (static device globals; no allocation allowed) ----
// Propagated states stored as y = dinv * x, fp16: 8 uint4 (32 uints) per node row.
__device__ __align__(16) unsigned g_E[NUM_NODES * 32];  // y0 = dinv*emb
__device__ __align__(16) unsigned g_A[NUM_NODES * 32];  // y1
__device__ __align__(16) unsigned g_B[NUM_NODES * 32];  // y2
__device__ float g_dinv[NUM_NODES];
__device__ int   g_deg[NUM_NODES];
__device__ int   g_row[NUM_NODES];      // CSR offsets (bumped in place by fill)
__device__ int   g_tile[NUM_TILES];
__device__ int   g_tpfx[NUM_TILES];
__device__ int   g_csrc[NUM_EDGES];     // CSR: src per slot (no weight needed)

__global__ void init_kernel() {
    int i = blockIdx.x * blockDim.x + threadIdx.x;
    if (i < NUM_NODES) g_deg[i] = 0;
}

__global__ void deg_kernel(const int* __restrict__ dst) {
    int e = blockIdx.x * blockDim.x + threadIdx.x;
    if (e < NUM_EDGES) atomicAdd(&g_deg[dst[e]], 1);
}

// per-tile exclusive scan of deg -> g_row (warp shuffles), also emit dinv
__global__ void scan_tiles() {
    __shared__ int wsum[32];
    int i = blockIdx.x * TILE + threadIdx.x;
    int lane = threadIdx.x & 31;
    int wid  = threadIdx.x >> 5;
    int v = (i < NUM_NODES) ? g_deg[i] : 0;
    if (i < NUM_NODES) g_dinv[i] = (v > 0) ? rsqrtf((float)v) : 0.0f;

    int x = v;
    #pragma unroll
    for (int off = 1; off < 32; off <<= 1) {
        int t = __shfl_up_sync(0xffffffffu, x, off);
        if (lane >= off) x += t;
    }
    if (lane == 31) wsum[wid] = x;
    __syncthreads();
    if (wid == 0) {
        int y = wsum[lane];
        #pragma unroll
        for (int off = 1; off < 32; off <<= 1) {
            int t = __shfl_up_sync(0xffffffffu, y, off);
            if (lane >= off) y += t;
        }
        wsum[lane] = y;
    }
    __syncthreads();
    int base = (wid > 0) ? wsum[wid - 1] : 0;
    if (i < NUM_NODES) g_row[i] = base + x - v;   // exclusive within tile
    if (threadIdx.x == TILE - 1) g_tile[blockIdx.x] = wsum[31];
}

__global__ void scan_tilesums() {            // 1 block, 128 threads
    __shared__ int wsum[4];
    int t = threadIdx.x;
    int lane = t & 31, wid = t >> 5;
    int v = (t < NUM_TILES) ? g_tile[t] : 0;
    int x = v;
    #pragma unroll
    for (int off = 1; off < 32; off <<= 1) {
        int a = __shfl_up_sync(0xffffffffu, x, off);
        if (lane >= off) x += a;
    }
    if (lane == 31) wsum[wid] = x;
    __syncthreads();
    int base = 0;
    for (int k = 0; k < wid; k++) base += wsum[k];
    if (t < NUM_TILES) g_tpfx[t] = base + x - v;
}

__global__ void scan_apply() {
    int i = blockIdx.x * blockDim.x + threadIdx.x;
    if (i < NUM_NODES) g_row[i] += g_tpfx[i / TILE];
}

// bucket edges by dst, bumping g_row in place (after: g_row[d] == row end)
__global__ void fill_kernel(const int* __restrict__ src, const int* __restrict__ dst) {
    int e = blockIdx.x * blockDim.x + threadIdx.x;
    if (e >= NUM_EDGES) return;
    int pos = atomicAdd(&g_row[dst[e]], 1);
    g_csrc[pos] = src[e];
}

// E = fp16(dinv[node] * emb)
__global__ void convert_kernel(const float4* __restrict__ emb4) {
    int i = blockIdx.x * blockDim.x + threadIdx.x;
    if (i >= NUM_NODES * 16) return;
    float dv = __ldg(&g_dinv[i >> 4]);
    float4 v = __ldg(&emb4[i]);
    __half2 lo = __floats2half2_rn(v.x * dv, v.y * dv);
    __half2 hi = __floats2half2_rn(v.z * dv, v.w * dv);
    uint2 p;
    p.x = *reinterpret_cast<unsigned*>(&lo);
    p.y = *reinterpret_cast<unsigned*>(&hi);
    reinterpret_cast<uint2*>(g_E)[i] = p;
}

__device__ __forceinline__ float2 h2f(unsigned u) {
    __half2 h = *reinterpret_cast<__half2*>(&u);
    return __half22float2(h);
}

// Pull in y-space: sum = Σ_{s∈N(g)} y_in[s].
// 8 threads per dst node, one uint4 (8 halves) each — a warp's gather
// instruction covers 4 distinct 128B lines (this was the R4 win).
//   layer 0: E -> A:  y1 = sum / deg
//   layer 1: A -> B:  y2 = sum / deg
//   layer 2: out = (emb + sqrt(deg)*(y1+y2) + dinv*sum) * 0.25
__global__ void __launch_bounds__(256) pull_kernel(const float4* __restrict__ emb4,
                                                   float4* __restrict__ out4,
                                                   int layer) {
    int g = blockIdx.x * (blockDim.x >> 3) + (threadIdx.x >> 3);  // dst node
    int c = threadIdx.x & 7;                                      // uint4 lane
    if (g >= NUM_NODES) return;

    const uint4* xin;
    if (layer == 0)      xin = (const uint4*)g_E;
    else if (layer == 1) xin = (const uint4*)g_A;
    else                 xin = (const uint4*)g_B;

    int beg = (g == 0) ? 0 : __ldg(&g_row[g - 1]);
    int end = __ldg(&g_row[g]);

    float acc[8] = {0.f, 0.f, 0.f, 0.f, 0.f, 0.f, 0.f, 0.f};

    int e = beg;
    for (; e + 4 <= end; e += 4) {          // 4-way unroll for MLP vs L2 latency
        int s0 = __ldg(&g_csrc[e]);
        int s1 = __ldg(&g_csrc[e + 1]);
        int s2 = __ldg(&g_csrc[e + 2]);
        int s3 = __ldg(&g_csrc[e + 3]);
        uint4 v0 = __ldg(&xin[s0 * 8 + c]);
        uint4 v1 = __ldg(&xin[s1 * 8 + c]);
        uint4 v2 = __ldg(&xin[s2 * 8 + c]);
        uint4 v3 = __ldg(&xin[s3 * 8 + c]);
        float2 f;
        f = h2f(v0.x); acc[0] += f.x; acc[1] += f.y;
        f = h2f(v0.y); acc[2] += f.x; acc[3] += f.y;
        f = h2f(v0.z); acc[4] += f.x; acc[5] += f.y;
        f = h2f(v0.w); acc[6] += f.x; acc[7] += f.y;
        f = h2f(v1.x); acc[0] += f.x; acc[1] += f.y;
        f = h2f(v1.y); acc[2] += f.x; acc[3] += f.y;
        f = h2f(v1.z); acc[4] += f.x; acc[5] += f.y;
        f = h2f(v1.w); acc[6] += f.x; acc[7] += f.y;
        f = h2f(v2.x); acc[0] += f.x; acc[1] += f.y;
        f = h2f(v2.y); acc[2] += f.x; acc[3] += f.y;
        f = h2f(v2.z); acc[4] += f.x; acc[5] += f.y;
        f = h2f(v2.w); acc[6] += f.x; acc[7] += f.y;
        f = h2f(v3.x); acc[0] += f.x; acc[1] += f.y;
        f = h2f(v3.y); acc[2] += f.x; acc[3] += f.y;
        f = h2f(v3.z); acc[4] += f.x; acc[5] += f.y;
        f = h2f(v3.w); acc[6] += f.x; acc[7] += f.y;
    }
    for (; e < end; e++) {
        int s0 = __ldg(&g_csrc[e]);
        uint4 v0 = __ldg(&xin[s0 * 8 + c]);
        float2 f;
        f = h2f(v0.x); acc[0] += f.x; acc[1] += f.y;
        f = h2f(v0.y); acc[2] += f.x; acc[3] += f.y;
        f = h2f(v0.z); acc[4] += f.x; acc[5] += f.y;
        f = h2f(v0.w); acc[6] += f.x; acc[7] += f.y;
    }

    if (layer < 2) {
        float dv = __ldg(&g_dinv[g]);
        float inv_deg = dv * dv;            // 1/deg (0 if deg==0)
        __half2 h0 = __floats2half2_rn(acc[0] * inv_deg, acc[1] * inv_deg);
        __half2 h1 = __floats2half2_rn(acc[2] * inv_deg, acc[3] * inv_deg);
        __half2 h2 = __floats2half2_rn(acc[4] * inv_deg, acc[5] * inv_deg);
        __half2 h3 = __floats2half2_rn(acc[6] * inv_deg, acc[7] * inv_deg);
        uint4 p;
        p.x = *reinterpret_cast<unsigned*>(&h0);
        p.y = *reinterpret_cast<unsigned*>(&h1);
        p.z = *reinterpret_cast<unsigned*>(&h2);
        p.w = *reinterpret_cast<unsigned*>(&h3);
        uint4* xout = (layer == 0) ? (uint4*)g_A : (uint4*)g_B;
        xout[g * 8 + c] = p;
    } else {
        float dv = __ldg(&g_dinv[g]);
        float sq = sqrtf((float)__ldg(&g_deg[g]));   // sqrt(deg)
        uint4 ap = ((const uint4*)g_A)[g * 8 + c];
        uint4 bp = ((const uint4*)g_B)[g * 8 + c];
        float2 a0 = h2f(ap.x), a1 = h2f(ap.y), a2 = h2f(ap.z), a3 = h2f(ap.w);
        float2 b0 = h2f(bp.x), b1 = h2f(bp.y), b2 = h2f(bp.z), b3 = h2f(bp.w);
        int base = g * 16 + c * 2;          // float4 index into emb/out
        float4 e0 = __ldg(&emb4[base]);
        float4 e1 = __ldg(&emb4[base + 1]);
        float4 r0, r1;
        r0.x = (e0.x + sq * (a0.x + b0.x) + dv * acc[0]) * 0.25f;
        r0.y = (e0.y + sq * (a0.y + b0.y) + dv * acc[1]) * 0.25f;
        r0.z = (e0.z + sq * (a1.x + b1.x) + dv * acc[2]) * 0.25f;
        r0.w = (e0.w + sq * (a1.y + b1.y) + dv * acc[3]) * 0.25f;
        r1.x = (e1.x + sq * (a2.x + b2.x) + dv * acc[4]) * 0.25f;
        r1.y = (e1.y + sq * (a2.y + b2.y) + dv * acc[5]) * 0.25f;
        r1.z = (e1.z + sq * (a3.x + b3.x) + dv * acc[6]) * 0.25f;
        r1.w = (e1.w + sq * (a3.y + b3.y) + dv * acc[7]) * 0.25f;
        out4[base]     = r0;
        out4[base + 1] = r1;
    }
}

extern "C" void kernel_launch(void* const* d_in, const int* in_sizes, int n_in,
                              void* d_out, int out_size) {
    const int*   edge = (const int*)d_in[0];   // [2, NUM_EDGES]
    const float* emb  = (const float*)d_in[1]; // [NUM_NODES, EMB_DIM]
    const int* src = edge;
    const int* dst = edge + NUM_EDGES;
    const float4* emb4 = (const float4*)emb;
    float4* out4 = (float4*)d_out;

    const int TPB = 256;

    init_kernel<<<(NUM_NODES + TPB - 1) / TPB, TPB>>>();
    deg_kernel<<<(NUM_EDGES + TPB - 1) / TPB, TPB>>>(dst);

    scan_tiles<<<NUM_TILES, TILE>>>();
    scan_tilesums<<<1, 128>>>();
    scan_apply<<<(NUM_NODES + TPB - 1) / TPB, TPB>>>();

    convert_kernel<<<(NUM_NODES * 16 + TPB - 1) / TPB, TPB>>>(emb4);
    fill_kernel<<<(NUM_EDGES + TPB - 1) / TPB, TPB>>>(src, dst);

    const int nodes_per_block = TPB / 8;   // 32 nodes per block
    const int pull_blocks = (NUM_NODES + nodes_per_block - 1) / nodes_per_block;

    pull_kernel<<<pull_blocks, TPB>>>(emb4, out4, 0);  // E -> A
    pull_kernel<<<pull_blocks, TPB>>>(emb4, out4, 1);  // A -> B
    pull_kernel<<<pull_blocks, TPB>>>(emb4, out4, 2);  // B -> out (fused)
}

// round 8
// speedup vs baseline: 1.6664x; 1.0259x over previous
#include <cuda_runtime.h>
#include <cuda_fp16.h>

#define NUM_NODES 100000
#define EMB_DIM   64
#define NUM_EDGES 1280000
#define TILE      1024
#define NUM_TILES ((NUM_NODES + TILE - 1) / TILE)   // 98

// ---- scratch (static device globals; no allocation allowed) ----
// Propagated states stored as y = dinv * x, fp16: 8 uint4 (32 uints) per node row.
__device__ __align__(16) unsigned g_E[NUM_NODES * 32];  // y0 = dinv*emb
__device__ __align__(16) unsigned g_A[NUM_NODES * 32];  // y1
__device__ __align__(16) unsigned g_B[NUM_NODES * 32];  // y2
__device__ float g_dinv[NUM_NODES];     // deg^-1/2 (0 if deg==0)
__device__ float g_sqd[NUM_NODES];      // deg^+1/2 (0 if deg==0)
__device__ int   g_deg[NUM_NODES];      // zero-init at load; self-cleaned each run
__device__ int   g_row[NUM_NODES];      // CSR offsets (bumped in place by fill)
__device__ int   g_tile[NUM_TILES];
__device__ int   g_csrc[NUM_EDGES];     // CSR: src per slot (no weight needed)

__global__ void deg_kernel(const int* __restrict__ dst) {
    int e = blockIdx.x * blockDim.x + threadIdx.x;
    if (e < NUM_EDGES) atomicAdd(&g_deg[dst[e]], 1);
}

// Per-tile exclusive scan of deg -> g_row (warp shuffles).
// Also: emit dinv & sqd, re-zero g_deg (self-cleaning for next run),
// and convert this tile's emb rows to fp16 y-space (fused old convert_kernel).
__global__ void scan_tiles(const float4* __restrict__ emb4) {
    __shared__ int   wsum[32];
    __shared__ float sdinv[TILE];
    int i    = blockIdx.x * TILE + threadIdx.x;
    int lane = threadIdx.x & 31;
    int wid  = threadIdx.x >> 5;

    int v = (i < NUM_NODES) ? g_deg[i] : 0;
    float dv = (v > 0) ? rsqrtf((float)v) : 0.0f;
    if (i < NUM_NODES) {
        g_dinv[i] = dv;
        g_sqd[i]  = (v > 0) ? sqrtf((float)v) : 0.0f;
        g_deg[i]  = 0;                      // clean for next invocation
    }
    sdinv[threadIdx.x] = dv;

    int x = v;                              // warp inclusive scan
    #pragma unroll
    for (int off = 1; off < 32; off <<= 1) {
        int t = __shfl_up_sync(0xffffffffu, x, off);
        if (lane >= off) x += t;
    }
    if (lane == 31) wsum[wid] = x;
    __syncthreads();
    if (wid == 0) {
        int y = wsum[lane];
        #pragma unroll
        for (int off = 1; off < 32; off <<= 1) {
            int t = __shfl_up_sync(0xffffffffu, y, off);
            if (lane >= off) y += t;
        }
        wsum[lane] = y;
    }
    __syncthreads();
    int base = (wid > 0) ? wsum[wid - 1] : 0;
    if (i < NUM_NODES) g_row[i] = base + x - v;       // exclusive within tile
    if (threadIdx.x == TILE - 1) g_tile[blockIdx.x] = wsum[31];

    // ---- fused convert: E[tile rows] = fp16(dinv * emb), coalesced float4 sweep
    int nbase = blockIdx.x * TILE;                    // first node of tile
    int fbase = nbase * 16;                           // float4 index of tile start
    #pragma unroll
    for (int k = 0; k < 16; k++) {
        int idx  = k * TILE + threadIdx.x;            // float4 offset within tile
        int node = nbase + (idx >> 4);
        if (node < NUM_NODES) {
            float d  = sdinv[idx >> 4];
            float4 val = __ldg(&emb4[fbase + idx]);
            __half2 lo = __floats2half2_rn(val.x * d, val.y * d);
            __half2 hi = __floats2half2_rn(val.z * d, val.w * d);
            uint2 p;
            p.x = *reinterpret_cast<unsigned*>(&lo);
            p.y = *reinterpret_cast<unsigned*>(&hi);
            reinterpret_cast<uint2*>(g_E)[fbase + idx] = p;
        }
    }
}

// Fused tile-prefix + apply: each 256-thread block lies in exactly one tile;
// it block-reduces g_tile[0..mytile) itself (NUM_TILES=98 <= 256 threads).
__global__ void scan_apply() {
    __shared__ int ssum[8];
    int mytile = blockIdx.x >> 2;                     // 256 TPB, TILE 1024
    int t = threadIdx.x;
    int lane = t & 31, w = t >> 5;

    int acc = (t < mytile) ? g_tile[t] : 0;           // mytile <= 97 < 256
    #pragma unroll
    for (int off = 16; off > 0; off >>= 1)
        acc += __shfl_down_sync(0xffffffffu, acc, off);
    if (lane == 0) ssum[w] = acc;
    __syncthreads();
    if (t == 0) {
        int s = 0;
        #pragma unroll
        for (int k = 0; k < 8; k++) s += ssum[k];
        ssum[0] = s;
    }
    __syncthreads();

    int i = blockIdx.x * 256 + t;
    if (i < NUM_NODES) g_row[i] += ssum[0];
}

// bucket edges by dst, bumping g_row in place (after: g_row[d] == row end)
__global__ void fill_kernel(const int* __restrict__ src, const int* __restrict__ dst) {
    int e = blockIdx.x * blockDim.x + threadIdx.x;
    if (e >= NUM_EDGES) return;
    int pos = atomicAdd(&g_row[dst[e]], 1);
    g_csrc[pos] = src[e];
}

__device__ __forceinline__ float2 h2f(unsigned u) {
    __half2 h = *reinterpret_cast<__half2*>(&u);
    return __half22float2(h);
}

// Pull in y-space: sum = Σ_{s∈N(g)} y_in[s].
// 8 threads per dst node, one uint4 (8 halves) each — a warp's gather
// instruction covers 4 distinct 128B lines.
//   layer 0: E -> A:  y1 = sum / deg
//   layer 1: A -> B:  y2 = sum / deg
//   layer 2: out = (emb + sqrt(deg)*(y1+y2) + dinv*sum) * 0.25
__global__ void __launch_bounds__(256) pull_kernel(const float4* __restrict__ emb4,
                                                   float4* __restrict__ out4,
                                                   int layer) {
    int g = blockIdx.x * (blockDim.x >> 3) + (threadIdx.x >> 3);  // dst node
    int c = threadIdx.x & 7;                                      // uint4 lane
    if (g >= NUM_NODES) return;

    const uint4* xin;
    if (layer == 0)      xin = (const uint4*)g_E;
    else if (layer == 1) xin = (const uint4*)g_A;
    else                 xin = (const uint4*)g_B;

    int beg = (g == 0) ? 0 : __ldg(&g_row[g - 1]);
    int end = __ldg(&g_row[g]);

    float acc[8] = {0.f, 0.f, 0.f, 0.f, 0.f, 0.f, 0.f, 0.f};

    int e = beg;
    for (; e + 4 <= end; e += 4) {          // 4-way unroll for MLP vs L2 latency
        int s0 = __ldg(&g_csrc[e]);
        int s1 = __ldg(&g_csrc[e + 1]);
        int s2 = __ldg(&g_csrc[e + 2]);
        int s3 = __ldg(&g_csrc[e + 3]);
        uint4 v0 = __ldg(&xin[s0 * 8 + c]);
        uint4 v1 = __ldg(&xin[s1 * 8 + c]);
        uint4 v2 = __ldg(&xin[s2 * 8 + c]);
        uint4 v3 = __ldg(&xin[s3 * 8 + c]);
        float2 f;
        f = h2f(v0.x); acc[0] += f.x; acc[1] += f.y;
        f = h2f(v0.y); acc[2] += f.x; acc[3] += f.y;
        f = h2f(v0.z); acc[4] += f.x; acc[5] += f.y;
        f = h2f(v0.w); acc[6] += f.x; acc[7] += f.y;
        f = h2f(v1.x); acc[0] += f.x; acc[1] += f.y;
        f = h2f(v1.y); acc[2] += f.x; acc[3] += f.y;
        f = h2f(v1.z); acc[4] += f.x; acc[5] += f.y;
        f = h2f(v1.w); acc[6] += f.x; acc[7] += f.y;
        f = h2f(v2.x); acc[0] += f.x; acc[1] += f.y;
        f = h2f(v2.y); acc[2] += f.x; acc[3] += f.y;
        f = h2f(v2.z); acc[4] += f.x; acc[5] += f.y;
        f = h2f(v2.w); acc[6] += f.x; acc[7] += f.y;
        f = h2f(v3.x); acc[0] += f.x; acc[1] += f.y;
        f = h2f(v3.y); acc[2] += f.x; acc[3] += f.y;
        f = h2f(v3.z); acc[4] += f.x; acc[5] += f.y;
        f = h2f(v3.w); acc[6] += f.x; acc[7] += f.y;
    }
    for (; e < end; e++) {
        int s0 = __ldg(&g_csrc[e]);
        uint4 v0 = __ldg(&xin[s0 * 8 + c]);
        float2 f;
        f = h2f(v0.x); acc[0] += f.x; acc[1] += f.y;
        f = h2f(v0.y); acc[2] += f.x; acc[3] += f.y;
        f = h2f(v0.z); acc[4] += f.x; acc[5] += f.y;
        f = h2f(v0.w); acc[6] += f.x; acc[7] += f.y;
    }

    if (layer < 2) {
        float dv = __ldg(&g_dinv[g]);
        float inv_deg = dv * dv;            // 1/deg (0 if deg==0)
        __half2 h0 = __floats2half2_rn(acc[0] * inv_deg, acc[1] * inv_deg);
        __half2 h1 = __floats2half2_rn(acc[2] * inv_deg, acc[3] * inv_deg);
        __half2 h2 = __floats2half2_rn(acc[4] * inv_deg, acc[5] * inv_deg);
        __half2 h3 = __floats2half2_rn(acc[6] * inv_deg, acc[7] * inv_deg);
        uint4 p;
        p.x = *reinterpret_cast<unsigned*>(&h0);
        p.y = *reinterpret_cast<unsigned*>(&h1);
        p.z = *reinterpret_cast<unsigned*>(&h2);
        p.w = *reinterpret_cast<unsigned*>(&h3);
        uint4* xout = (layer == 0) ? (uint4*)g_A : (uint4*)g_B;
        xout[g * 8 + c] = p;
    } else {
        float dv = __ldg(&g_dinv[g]);
        float sq = __ldg(&g_sqd[g]);        // sqrt(deg), 0 if deg==0
        uint4 ap = ((const uint4*)g_A)[g * 8 + c];
        uint4 bp = ((const uint4*)g_B)[g * 8 + c];
        float2 a0 = h2f(ap.x), a1 = h2f(ap.y), a2 = h2f(ap.z), a3 = h2f(ap.w);
        float2 b0 = h2f(bp.x), b1 = h2f(bp.y), b2 = h2f(bp.z), b3 = h2f(bp.w);
        int base = g * 16 + c * 2;          // float4 index into emb/out
        float4 e0 = __ldg(&emb4[base]);
        float4 e1 = __ldg(&emb4[base + 1]);
        float4 r0, r1;
        r0.x = (e0.x + sq * (a0.x + b0.x) + dv * acc[0]) * 0.25f;
        r0.y = (e0.y + sq * (a0.y + b0.y) + dv * acc[1]) * 0.25f;
        r0.z = (e0.z + sq * (a1.x + b1.x) + dv * acc[2]) * 0.25f;
        r0.w = (e0.w + sq * (a1.y + b1.y) + dv * acc[3]) * 0.25f;
        r1.x = (e1.x + sq * (a2.x + b2.x) + dv * acc[4]) * 0.25f;
        r1.y = (e1.y + sq * (a2.y + b2.y) + dv * acc[5]) * 0.25f;
        r1.z = (e1.z + sq * (a3.x + b3.x) + dv * acc[6]) * 0.25f;
        r1.w = (e1.w + sq * (a3.y + b3.y) + dv * acc[7]) * 0.25f;
        out4[base]     = r0;
        out4[base + 1] = r1;
    }
}

extern "C" void kernel_launch(void* const* d_in, const int* in_sizes, int n_in,
                              void* d_out, int out_size) {
    const int*   edge = (const int*)d_in[0];   // [2, NUM_EDGES]
    const float* emb  = (const float*)d_in[1]; // [NUM_NODES, EMB_DIM]
    const int* src = edge;
    const int* dst = edge + NUM_EDGES;
    const float4* emb4 = (const float4*)emb;
    float4* out4 = (float4*)d_out;

    const int TPB = 256;

    // g_deg is zero at module load and re-zeroed by scan_tiles each run.
    deg_kernel<<<(NUM_EDGES + TPB - 1) / TPB, TPB>>>(dst);
    scan_tiles<<<NUM_TILES, TILE>>>(emb4);        // dinv/sqd + scan + convert + deg-clean
    scan_apply<<<(NUM_NODES + 255) / 256, 256>>>();
    fill_kernel<<<(NUM_EDGES + TPB - 1) / TPB, TPB>>>(src, dst);

    const int nodes_per_block = TPB / 8;   // 32 nodes per block
    const int pull_blocks = (NUM_NODES + nodes_per_block - 1) / nodes_per_block;

    pull_kernel<<<pull_blocks, TPB>>>(emb4, out4, 0);  // E -> A
    pull_kernel<<<pull_blocks, TPB>>>(emb4, out4, 1);  // A -> B
    pull_kernel<<<pull_blocks, TPB>>>(emb4, out4, 2);  // B -> out (fused)
}

// round 9
// speedup vs baseline: 1.6676x; 1.0007x over previous
#include <cuda_runtime.h>
#include <cuda_fp16.h>

#define NUM_NODES 100000
#define EMB_DIM   64
#define NUM_EDGES 1280000
#define TILE      1024
#define NUM_TILES ((NUM_NODES + TILE - 1) / TILE)   // 98

// ---- scratch (static device globals; no allocation allowed) ----
// Propagated states stored as y = dinv * x, fp16: 8 uint4 (32 uints) per node row.
__device__ __align__(16) unsigned g_E[NUM_NODES * 32];  // y0 = dinv*emb
__device__ __align__(16) unsigned g_A[NUM_NODES * 32];  // y1
__device__ __align__(16) unsigned g_B[NUM_NODES * 32];  // y2
__device__ float g_dinv[NUM_NODES];     // deg^-1/2 (0 if deg==0)
__device__ float g_sqd[NUM_NODES];      // deg^+1/2 (0 if deg==0)
__device__ int   g_deg[NUM_NODES];      // zero-init at load; self-cleaned each run
__device__ int   g_row[NUM_NODES];      // CSR offsets (bumped in place by fill)
__device__ int   g_tile[NUM_TILES];
__device__ int   g_csrc[NUM_EDGES];     // CSR: src per slot (no weight needed)

__global__ void deg_kernel(const int* __restrict__ dst) {
    int e = blockIdx.x * blockDim.x + threadIdx.x;
    if (e < NUM_EDGES) atomicAdd(&g_deg[dst[e]], 1);
}

// Per-tile exclusive scan of deg -> g_row (warp shuffles).
// Also: emit dinv & sqd, re-zero g_deg (self-cleaning for next run),
// and convert this tile's emb rows to fp16 y-space (fused old convert_kernel).
__global__ void scan_tiles(const float4* __restrict__ emb4) {
    __shared__ int   wsum[32];
    __shared__ float sdinv[TILE];
    int i    = blockIdx.x * TILE + threadIdx.x;
    int lane = threadIdx.x & 31;
    int wid  = threadIdx.x >> 5;

    int v = (i < NUM_NODES) ? g_deg[i] : 0;
    float dv = (v > 0) ? rsqrtf((float)v) : 0.0f;
    if (i < NUM_NODES) {
        g_dinv[i] = dv;
        g_sqd[i]  = (v > 0) ? sqrtf((float)v) : 0.0f;
        g_deg[i]  = 0;                      // clean for next invocation
    }
    sdinv[threadIdx.x] = dv;

    int x = v;                              // warp inclusive scan
    #pragma unroll
    for (int off = 1; off < 32; off <<= 1) {
        int t = __shfl_up_sync(0xffffffffu, x, off);
        if (lane >= off) x += t;
    }
    if (lane == 31) wsum[wid] = x;
    __syncthreads();
    if (wid == 0) {
        int y = wsum[lane];
        #pragma unroll
        for (int off = 1; off < 32; off <<= 1) {
            int t = __shfl_up_sync(0xffffffffu, y, off);
            if (lane >= off) y += t;
        }
        wsum[lane] = y;
    }
    __syncthreads();
    int base = (wid > 0) ? wsum[wid - 1] : 0;
    if (i < NUM_NODES) g_row[i] = base + x - v;       // exclusive within tile
    if (threadIdx.x == TILE - 1) g_tile[blockIdx.x] = wsum[31];

    // ---- fused convert: E[tile rows] = fp16(dinv * emb), coalesced float4 sweep
    int nbase = blockIdx.x * TILE;                    // first node of tile
    int fbase = nbase * 16;                           // float4 index of tile start
    #pragma unroll
    for (int k = 0; k < 16; k++) {
        int idx  = k * TILE + threadIdx.x;            // float4 offset within tile
        int node = nbase + (idx >> 4);
        if (node < NUM_NODES) {
            float d  = sdinv[idx >> 4];
            float4 val = __ldg(&emb4[fbase + idx]);
            __half2 lo = __floats2half2_rn(val.x * d, val.y * d);
            __half2 hi = __floats2half2_rn(val.z * d, val.w * d);
            uint2 p;
            p.x = *reinterpret_cast<unsigned*>(&lo);
            p.y = *reinterpret_cast<unsigned*>(&hi);
            reinterpret_cast<uint2*>(g_E)[fbase + idx] = p;
        }
    }
}

// Fused tile-prefix + apply: each 256-thread block lies in exactly one tile;
// it block-reduces g_tile[0..mytile) itself (NUM_TILES=98 <= 256 threads).
__global__ void scan_apply() {
    __shared__ int ssum[8];
    int mytile = blockIdx.x >> 2;                     // 256 TPB, TILE 1024
    int t = threadIdx.x;
    int lane = t & 31, w = t >> 5;

    int acc = (t < mytile) ? g_tile[t] : 0;           // mytile <= 97 < 256
    #pragma unroll
    for (int off = 16; off > 0; off >>= 1)
        acc += __shfl_down_sync(0xffffffffu, acc, off);
    if (lane == 0) ssum[w] = acc;
    __syncthreads();
    if (t == 0) {
        int s = 0;
        #pragma unroll
        for (int k = 0; k < 8; k++) s += ssum[k];
        ssum[0] = s;
    }
    __syncthreads();

    int i = blockIdx.x * 256 + t;
    if (i < NUM_NODES) g_row[i] += ssum[0];
}

// bucket edges by dst, bumping g_row in place (after: g_row[d] == row end)
__global__ void fill_kernel(const int* __restrict__ src, const int* __restrict__ dst) {
    int e = blockIdx.x * blockDim.x + threadIdx.x;
    if (e >= NUM_EDGES) return;
    int pos = atomicAdd(&g_row[dst[e]], 1);
    g_csrc[pos] = src[e];
}

__device__ __forceinline__ float2 h2f(unsigned u) {
    __half2 h = *reinterpret_cast<__half2*>(&u);
    return __half22float2(h);
}

// Pull in y-space: sum = Σ_{s∈N(g)} y_in[s].
// 8 threads per dst node, one uint4 (8 halves) each — a warp's gather
// instruction covers 4 distinct 128B lines.
//   layer 0: E -> A:  y1 = sum / deg
//   layer 1: A -> B:  y2 = sum / deg
//   layer 2: out = (emb + sqrt(deg)*(y1+y2) + dinv*sum) * 0.25
__global__ void __launch_bounds__(256) pull_kernel(const float4* __restrict__ emb4,
                                                   float4* __restrict__ out4,
                                                   int layer) {
    int g = blockIdx.x * (blockDim.x >> 3) + (threadIdx.x >> 3);  // dst node
    int c = threadIdx.x & 7;                                      // uint4 lane
    if (g >= NUM_NODES) return;

    const uint4* xin;
    if (layer == 0)      xin = (const uint4*)g_E;
    else if (layer == 1) xin = (const uint4*)g_A;
    else                 xin = (const uint4*)g_B;

    int beg = (g == 0) ? 0 : __ldg(&g_row[g - 1]);
    int end = __ldg(&g_row[g]);

    float acc[8] = {0.f, 0.f, 0.f, 0.f, 0.f, 0.f, 0.f, 0.f};

    int e = beg;
    for (; e + 4 <= end; e += 4) {          // 4-way unroll for MLP vs L2 latency
        int s0 = __ldg(&g_csrc[e]);
        int s1 = __ldg(&g_csrc[e + 1]);
        int s2 = __ldg(&g_csrc[e + 2]);
        int s3 = __ldg(&g_csrc[e + 3]);
        uint4 v0 = __ldg(&xin[s0 * 8 + c]);
        uint4 v1 = __ldg(&xin[s1 * 8 + c]);
        uint4 v2 = __ldg(&xin[s2 * 8 + c]);
        uint4 v3 = __ldg(&xin[s3 * 8 + c]);
        float2 f;
        f = h2f(v0.x); acc[0] += f.x; acc[1] += f.y;
        f = h2f(v0.y); acc[2] += f.x; acc[3] += f.y;
        f = h2f(v0.z); acc[4] += f.x; acc[5] += f.y;
        f = h2f(v0.w); acc[6] += f.x; acc[7] += f.y;
        f = h2f(v1.x); acc[0] += f.x; acc[1] += f.y;
        f = h2f(v1.y); acc[2] += f.x; acc[3] += f.y;
        f = h2f(v1.z); acc[4] += f.x; acc[5] += f.y;
        f = h2f(v1.w); acc[6] += f.x; acc[7] += f.y;
        f = h2f(v2.x); acc[0] += f.x; acc[1] += f.y;
        f = h2f(v2.y); acc[2] += f.x; acc[3] += f.y;
        f = h2f(v2.z); acc[4] += f.x; acc[5] += f.y;
        f = h2f(v2.w); acc[6] += f.x; acc[7] += f.y;
        f = h2f(v3.x); acc[0] += f.x; acc[1] += f.y;
        f = h2f(v3.y); acc[2] += f.x; acc[3] += f.y;
        f = h2f(v3.z); acc[4] += f.x; acc[5] += f.y;
        f = h2f(v3.w); acc[6] += f.x; acc[7] += f.y;
    }
    for (; e < end; e++) {
        int s0 = __ldg(&g_csrc[e]);
        uint4 v0 = __ldg(&xin[s0 * 8 + c]);
        float2 f;
        f = h2f(v0.x); acc[0] += f.x; acc[1] += f.y;
        f = h2f(v0.y); acc[2] += f.x; acc[3] += f.y;
        f = h2f(v0.z); acc[4] += f.x; acc[5] += f.y;
        f = h2f(v0.w); acc[6] += f.x; acc[7] += f.y;
    }

    if (layer < 2) {
        float dv = __ldg(&g_dinv[g]);
        float inv_deg = dv * dv;            // 1/deg (0 if deg==0)
        __half2 h0 = __floats2half2_rn(acc[0] * inv_deg, acc[1] * inv_deg);
        __half2 h1 = __floats2half2_rn(acc[2] * inv_deg, acc[3] * inv_deg);
        __half2 h2 = __floats2half2_rn(acc[4] * inv_deg, acc[5] * inv_deg);
        __half2 h3 = __floats2half2_rn(acc[6] * inv_deg, acc[7] * inv_deg);
        uint4 p;
        p.x = *reinterpret_cast<unsigned*>(&h0);
        p.y = *reinterpret_cast<unsigned*>(&h1);
        p.z = *reinterpret_cast<unsigned*>(&h2);
        p.w = *reinterpret_cast<unsigned*>(&h3);
        uint4* xout = (layer == 0) ? (uint4*)g_A : (uint4*)g_B;
        xout[g * 8 + c] = p;
    } else {
        float dv = __ldg(&g_dinv[g]);
        float sq = __ldg(&g_sqd[g]);        // sqrt(deg), 0 if deg==0
        uint4 ap = ((const uint4*)g_A)[g * 8 + c];
        uint4 bp = ((const uint4*)g_B)[g * 8 + c];
        float2 a0 = h2f(ap.x), a1 = h2f(ap.y), a2 = h2f(ap.z), a3 = h2f(ap.w);
        float2 b0 = h2f(bp.x), b1 = h2f(bp.y), b2 = h2f(bp.z), b3 = h2f(bp.w);
        int base = g * 16 + c * 2;          // float4 index into emb/out
        float4 e0 = __ldg(&emb4[base]);
        float4 e1 = __ldg(&emb4[base + 1]);
        float4 r0, r1;
        r0.x = (e0.x + sq * (a0.x + b0.x) + dv * acc[0]) * 0.25f;
        r0.y = (e0.y + sq * (a0.y + b0.y) + dv * acc[1]) * 0.25f;
        r0.z = (e0.z + sq * (a1.x + b1.x) + dv * acc[2]) * 0.25f;
        r0.w = (e0.w + sq * (a1.y + b1.y) + dv * acc[3]) * 0.25f;
        r1.x = (e1.x + sq * (a2.x + b2.x) + dv * acc[4]) * 0.25f;
        r1.y = (e1.y + sq * (a2.y + b2.y) + dv * acc[5]) * 0.25f;
        r1.z = (e1.z + sq * (a3.x + b3.x) + dv * acc[6]) * 0.25f;
        r1.w = (e1.w + sq * (a3.y + b3.y) + dv * acc[7]) * 0.25f;
        out4[base]     = r0;
        out4[base + 1] = r1;
    }
}

extern "C" void kernel_launch(void* const* d_in, const int* in_sizes, int n_in,
                              void* d_out, int out_size) {
    const int*   edge = (const int*)d_in[0];   // [2, NUM_EDGES]
    const float* emb  = (const float*)d_in[1]; // [NUM_NODES, EMB_DIM]
    const int* src = edge;
    const int* dst = edge + NUM_EDGES;
    const float4* emb4 = (const float4*)emb;
    float4* out4 = (float4*)d_out;

    const int TPB = 256;

    // g_deg is zero at module load and re-zeroed by scan_tiles each run.
    deg_kernel<<<(NUM_EDGES + TPB - 1) / TPB, TPB>>>(dst);
    scan_tiles<<<NUM_TILES, TILE>>>(emb4);        // dinv/sqd + scan + convert + deg-clean
    scan_apply<<<(NUM_NODES + 255) / 256, 256>>>();
    fill_kernel<<<(NUM_EDGES + TPB - 1) / TPB, TPB>>>(src, dst);

    const int nodes_per_block = TPB / 8;   // 32 nodes per block
    const int pull_blocks = (NUM_NODES + nodes_per_block - 1) / nodes_per_block;

    pull_kernel<<<pull_blocks, TPB>>>(emb4, out4, 0);  // E -> A
    pull_kernel<<<pull_blocks, TPB>>>(emb4, out4, 1);  // A -> B
    pull_kernel<<<pull_blocks, TPB>>>(emb4, out4, 2);  // B -> out (fused)
}

// round 10
// speedup vs baseline: 1.6692x; 1.0010x over previous
#include <cuda_runtime.h>
#include <cuda_fp16.h>

#define NUM_NODES 100000
#define EMB_DIM   64
#define NUM_EDGES 1280000
#define TILE      1024
#define NUM_TILES ((NUM_NODES + TILE - 1) / TILE)   // 98

// ---- scratch (static device globals; no allocation allowed) ----
// Propagated states stored as y = dinv * x, fp16: 8 uint4 (32 uints) per node row.
__device__ __align__(16) unsigned g_E[NUM_NODES * 32];  // y0 = dinv*emb
__device__ __align__(16) unsigned g_A[NUM_NODES * 32];  // y1
__device__ __align__(16) unsigned g_B[NUM_NODES * 32];  // y2
__device__ float g_dinv[NUM_NODES];          // deg^-1/2 (0 if deg==0)
__device__ float g_sqd[NUM_NODES];           // deg^+1/2 (0 if deg==0)
__device__ int   g_deg[NUM_NODES];           // zero at load; self-cleaned each run
__device__ int   g_row[NUM_NODES + 1];       // CSR exclusive starts; [NUM_NODES]=E
__device__ int   g_tile[NUM_TILES];
__device__ unsigned short g_rank[NUM_EDGES]; // per-edge rank within dst bucket
__device__ int   g_csrc[NUM_EDGES];          // CSR: src per slot

// deg[dst]++ AND record each edge's rank within its bucket (old counter value).
__global__ void deg_kernel(const int* __restrict__ dst) {
    int e = blockIdx.x * blockDim.x + threadIdx.x;
    if (e < NUM_EDGES) {
        int r = atomicAdd(&g_deg[dst[e]], 1);
        g_rank[e] = (unsigned short)r;
    }
}

// Per-tile exclusive scan of deg -> g_row (warp shuffles).
// Also: emit dinv & sqd, re-zero g_deg, and convert this tile's emb rows to
// fp16 y-space (fused convert).
__global__ void scan_tiles(const float4* __restrict__ emb4) {
    __shared__ int   wsum[32];
    __shared__ float sdinv[TILE];
    int i    = blockIdx.x * TILE + threadIdx.x;
    int lane = threadIdx.x & 31;
    int wid  = threadIdx.x >> 5;

    int v = (i < NUM_NODES) ? g_deg[i] : 0;
    float dv = (v > 0) ? rsqrtf((float)v) : 0.0f;
    if (i < NUM_NODES) {
        g_dinv[i] = dv;
        g_sqd[i]  = (v > 0) ? sqrtf((float)v) : 0.0f;
        g_deg[i]  = 0;                      // clean for next invocation
    }
    sdinv[threadIdx.x] = dv;

    int x = v;                              // warp inclusive scan
    #pragma unroll
    for (int off = 1; off < 32; off <<= 1) {
        int t = __shfl_up_sync(0xffffffffu, x, off);
        if (lane >= off) x += t;
    }
    if (lane == 31) wsum[wid] = x;
    __syncthreads();
    if (wid == 0) {
        int y = wsum[lane];
        #pragma unroll
        for (int off = 1; off < 32; off <<= 1) {
            int t = __shfl_up_sync(0xffffffffu, y, off);
            if (lane >= off) y += t;
        }
        wsum[lane] = y;
    }
    __syncthreads();
    int base = (wid > 0) ? wsum[wid - 1] : 0;
    if (i < NUM_NODES) g_row[i] = base + x - v;       // exclusive within tile
    if (threadIdx.x == TILE - 1) g_tile[blockIdx.x] = wsum[31];

    // ---- fused convert: E[tile rows] = fp16(dinv * emb), coalesced float4 sweep
    int nbase = blockIdx.x * TILE;
    int fbase = nbase * 16;
    #pragma unroll
    for (int k = 0; k < 16; k++) {
        int idx  = k * TILE + threadIdx.x;
        int node = nbase + (idx >> 4);
        if (node < NUM_NODES) {
            float d  = sdinv[idx >> 4];
            float4 val = __ldg(&emb4[fbase + idx]);
            __half2 lo = __floats2half2_rn(val.x * d, val.y * d);
            __half2 hi = __floats2half2_rn(val.z * d, val.w * d);
            uint2 p;
            p.x = *reinterpret_cast<unsigned*>(&lo);
            p.y = *reinterpret_cast<unsigned*>(&hi);
            reinterpret_cast<uint2*>(g_E)[fbase + idx] = p;
        }
    }
}

// Fused tile-prefix + apply: each 256-thread block lies in exactly one tile;
// block-reduces g_tile[0..mytile) itself. Also sets g_row[NUM_NODES].
__global__ void scan_apply() {
    __shared__ int ssum[8];
    int mytile = blockIdx.x >> 2;                     // 256 TPB, TILE 1024
    int t = threadIdx.x;
    int lane = t & 31, w = t >> 5;

    int acc = (t < mytile) ? g_tile[t] : 0;
    #pragma unroll
    for (int off = 16; off > 0; off >>= 1)
        acc += __shfl_down_sync(0xffffffffu, acc, off);
    if (lane == 0) ssum[w] = acc;
    __syncthreads();
    if (t == 0) {
        int s = 0;
        #pragma unroll
        for (int k = 0; k < 8; k++) s += ssum[k];
        ssum[0] = s;
    }
    __syncthreads();

    int i = blockIdx.x * 256 + t;
    if (i < NUM_NODES) g_row[i] += ssum[0];
    if (i == 0) g_row[NUM_NODES] = NUM_EDGES;
}

// Atomic-free fill: pos = row[dst[e]] + rank[e]. 4 edges/thread, phase-
// separated for MLP (the R7 fill was serialized on the ATOMG return value).
__global__ void fill_kernel(const int* __restrict__ src, const int* __restrict__ dst) {
    int base = (blockIdx.x * blockDim.x + threadIdx.x) * 4;
    if (base + 4 <= NUM_EDGES) {
        int d0 = __ldg(&dst[base]),     d1 = __ldg(&dst[base + 1]);
        int d2 = __ldg(&dst[base + 2]), d3 = __ldg(&dst[base + 3]);
        int s0 = __ldg(&src[base]),     s1 = __ldg(&src[base + 1]);
        int s2 = __ldg(&src[base + 2]), s3 = __ldg(&src[base + 3]);
        int r0 = g_rank[base],     r1 = g_rank[base + 1];
        int r2 = g_rank[base + 2], r3 = g_rank[base + 3];
        int p0 = __ldg(&g_row[d0]) + r0;
        int p1 = __ldg(&g_row[d1]) + r1;
        int p2 = __ldg(&g_row[d2]) + r2;
        int p3 = __ldg(&g_row[d3]) + r3;
        g_csrc[p0] = s0; g_csrc[p1] = s1; g_csrc[p2] = s2; g_csrc[p3] = s3;
    } else {
        for (int e = base; e < NUM_EDGES; e++) {
            int pos = __ldg(&g_row[dst[e]]) + (int)g_rank[e];
            g_csrc[pos] = src[e];
        }
    }
}

__device__ __forceinline__ float2 h2f(unsigned u) {
    __half2 h = *reinterpret_cast<__half2*>(&u);
    return __half22float2(h);
}

// Pull in y-space: sum = Σ_{s∈N(g)} y_in[s].
// 8 threads per dst node, one uint4 (8 halves) each — a warp's gather
// instruction covers 4 distinct 128B lines.
//   layer 0: E -> A:  y1 = sum / deg
//   layer 1: A -> B:  y2 = sum / deg
//   layer 2: out = (emb + sqrt(deg)*(y1+y2) + dinv*sum) * 0.25
__global__ void __launch_bounds__(256) pull_kernel(const float4* __restrict__ emb4,
                                                   float4* __restrict__ out4,
                                                   int layer) {
    int g = blockIdx.x * (blockDim.x >> 3) + (threadIdx.x >> 3);  // dst node
    int c = threadIdx.x & 7;                                      // uint4 lane
    if (g >= NUM_NODES) return;

    const uint4* xin;
    if (layer == 0)      xin = (const uint4*)g_E;
    else if (layer == 1) xin = (const uint4*)g_A;
    else                 xin = (const uint4*)g_B;

    int beg = __ldg(&g_row[g]);
    int end = __ldg(&g_row[g + 1]);

    float acc[8] = {0.f, 0.f, 0.f, 0.f, 0.f, 0.f, 0.f, 0.f};

    int e = beg;
    for (; e + 4 <= end; e += 4) {          // 4-way unroll for MLP vs L2 latency
        int s0 = __ldg(&g_csrc[e]);
        int s1 = __ldg(&g_csrc[e + 1]);
        int s2 = __ldg(&g_csrc[e + 2]);
        int s3 = __ldg(&g_csrc[e + 3]);
        uint4 v0 = __ldg(&xin[s0 * 8 + c]);
        uint4 v1 = __ldg(&xin[s1 * 8 + c]);
        uint4 v2 = __ldg(&xin[s2 * 8 + c]);
        uint4 v3 = __ldg(&xin[s3 * 8 + c]);
        float2 f;
        f = h2f(v0.x); acc[0] += f.x; acc[1] += f.y;
        f = h2f(v0.y); acc[2] += f.x; acc[3] += f.y;
        f = h2f(v0.z); acc[4] += f.x; acc[5] += f.y;
        f = h2f(v0.w); acc[6] += f.x; acc[7] += f.y;
        f = h2f(v1.x); acc[0] += f.x; acc[1] += f.y;
        f = h2f(v1.y); acc[2] += f.x; acc[3] += f.y;
        f = h2f(v1.z); acc[4] += f.x; acc[5] += f.y;
        f = h2f(v1.w); acc[6] += f.x; acc[7] += f.y;
        f = h2f(v2.x); acc[0] += f.x; acc[1] += f.y;
        f = h2f(v2.y); acc[2] += f.x; acc[3] += f.y;
        f = h2f(v2.z); acc[4] += f.x; acc[5] += f.y;
        f = h2f(v2.w); acc[6] += f.x; acc[7] += f.y;
        f = h2f(v3.x); acc[0] += f.x; acc[1] += f.y;
        f = h2f(v3.y); acc[2] += f.x; acc[3] += f.y;
        f = h2f(v3.z); acc[4] += f.x; acc[5] += f.y;
        f = h2f(v3.w); acc[6] += f.x; acc[7] += f.y;
    }
    for (; e < end; e++) {
        int s0 = __ldg(&g_csrc[e]);
        uint4 v0 = __ldg(&xin[s0 * 8 + c]);
        float2 f;
        f = h2f(v0.x); acc[0] += f.x; acc[1] += f.y;
        f = h2f(v0.y); acc[2] += f.x; acc[3] += f.y;
        f = h2f(v0.z); acc[4] += f.x; acc[5] += f.y;
        f = h2f(v0.w); acc[6] += f.x; acc[7] += f.y;
    }

    if (layer < 2) {
        float dv = __ldg(&g_dinv[g]);
        float inv_deg = dv * dv;            // 1/deg (0 if deg==0)
        __half2 h0 = __floats2half2_rn(acc[0] * inv_deg, acc[1] * inv_deg);
        __half2 h1 = __floats2half2_rn(acc[2] * inv_deg, acc[3] * inv_deg);
        __half2 h2 = __floats2half2_rn(acc[4] * inv_deg, acc[5] * inv_deg);
        __half2 h3 = __floats2half2_rn(acc[6] * inv_deg, acc[7] * inv_deg);
        uint4 p;
        p.x = *reinterpret_cast<unsigned*>(&h0);
        p.y = *reinterpret_cast<unsigned*>(&h1);
        p.z = *reinterpret_cast<unsigned*>(&h2);
        p.w = *reinterpret_cast<unsigned*>(&h3);
        uint4* xout = (layer == 0) ? (uint4*)g_A : (uint4*)g_B;
        xout[g * 8 + c] = p;
    } else {
        float dv = __ldg(&g_dinv[g]);
        float sq = __ldg(&g_sqd[g]);        // sqrt(deg)
        uint4 ap = ((const uint4*)g_A)[g * 8 + c];
        uint4 bp = ((const uint4*)g_B)[g * 8 + c];
        float2 a0 = h2f(ap.x), a1 = h2f(ap.y), a2 = h2f(ap.z), a3 = h2f(ap.w);
        float2 b0 = h2f(bp.x), b1 = h2f(bp.y), b2 = h2f(bp.z), b3 = h2f(bp.w);
        int base = g * 16 + c * 2;          // float4 index into emb/out
        float4 e0 = __ldg(&emb4[base]);
        float4 e1 = __ldg(&emb4[base + 1]);
        float4 r0, r1;
        r0.x = (e0.x + sq * (a0.x + b0.x) + dv * acc[0]) * 0.25f;
        r0.y = (e0.y + sq * (a0.y + b0.y) + dv * acc[1]) * 0.25f;
        r0.z = (e0.z + sq * (a1.x + b1.x) + dv * acc[2]) * 0.25f;
        r0.w = (e0.w + sq * (a1.y + b1.y) + dv * acc[3]) * 0.25f;
        r1.x = (e1.x + sq * (a2.x + b2.x) + dv * acc[4]) * 0.25f;
        r1.y = (e1.y + sq * (a2.y + b2.y) + dv * acc[5]) * 0.25f;
        r1.z = (e1.z + sq * (a3.x + b3.x) + dv * acc[6]) * 0.25f;
        r1.w = (e1.w + sq * (a3.y + b3.y) + dv * acc[7]) * 0.25f;
        out4[base]     = r0;
        out4[base + 1] = r1;
    }
}

extern "C" void kernel_launch(void* const* d_in, const int* in_sizes, int n_in,
                              void* d_out, int out_size) {
    const int*   edge = (const int*)d_in[0];   // [2, NUM_EDGES]
    const float* emb  = (const float*)d_in[1]; // [NUM_NODES, EMB_DIM]
    const int* src = edge;
    const int* dst = edge + NUM_EDGES;
    const float4* emb4 = (const float4*)emb;
    float4* out4 = (float4*)d_out;

    const int TPB = 256;

    // g_deg is zero at module load and re-zeroed by scan_tiles each run.
    deg_kernel<<<(NUM_EDGES + TPB - 1) / TPB, TPB>>>(dst);
    scan_tiles<<<NUM_TILES, TILE>>>(emb4);        // dinv/sqd + scan + convert + deg-clean
    scan_apply<<<(NUM_NODES + 255) / 256, 256>>>();
    fill_kernel<<<(NUM_EDGES / 4 + TPB - 1) / TPB, TPB>>>(src, dst);

    const int nodes_per_block = TPB / 8;   // 32 nodes per block
    const int pull_blocks = (NUM_NODES + nodes_per_block - 1) / nodes_per_block;

    pull_kernel<<<pull_blocks, TPB>>>(emb4, out4, 0);  // E -> A
    pull_kernel<<<pull_blocks, TPB>>>(emb4, out4, 1);  // A -> B
    pull_kernel<<<pull_blocks, TPB>>>(emb4, out4, 2);  // B -> out (fused)
}

// round 11
// speedup vs baseline: 1.6906x; 1.0128x over previous
#include <cuda_runtime.h>
#include <cuda_fp16.h>

#define NUM_NODES 100000
#define EMB_DIM   64
#define NUM_EDGES 1280000
#define CAP       64        // per-node bucket capacity (P(overflow) ~ 3e-18)
#define CAP_SHIFT 6

// ---- scratch (static device globals; no allocation allowed) ----
// Propagated states stored as y = dinv * x, fp16: 8 uint4 (32 uints) per node row.
__device__ __align__(16) unsigned g_E[NUM_NODES * 32];  // y0 = dinv*emb
__device__ __align__(16) unsigned g_A[NUM_NODES * 32];  // y1
__device__ __align__(16) unsigned g_B[NUM_NODES * 32];  // y2
__device__ float g_dinv[NUM_NODES];      // deg^-1/2 (0 if deg==0)
__device__ float g_sqd[NUM_NODES];       // deg^+1/2 (0 if deg==0)
__device__ int   g_deg[NUM_NODES];       // zero at load; self-cleaned by prep
__device__ int   g_degc[NUM_NODES];      // stable copy for the pull kernels
__device__ int   g_csp[NUM_NODES * CAP]; // padded CSR: src per slot

// Single-pass CSR build: rank from the atomic, direct store into the padded
// bucket. 4 edges/thread so the 4 ATOMG returns overlap (MLP=4 vs 318 cyc).
__global__ void build_kernel(const int* __restrict__ src, const int* __restrict__ dst) {
    int base = (blockIdx.x * blockDim.x + threadIdx.x) * 4;
    if (base + 4 <= NUM_EDGES) {
        int d0 = __ldg(&dst[base]),     d1 = __ldg(&dst[base + 1]);
        int d2 = __ldg(&dst[base + 2]), d3 = __ldg(&dst[base + 3]);
        int s0 = __ldg(&src[base]),     s1 = __ldg(&src[base + 1]);
        int s2 = __ldg(&src[base + 2]), s3 = __ldg(&src[base + 3]);
        int r0 = atomicAdd(&g_deg[d0], 1);
        int r1 = atomicAdd(&g_deg[d1], 1);
        int r2 = atomicAdd(&g_deg[d2], 1);
        int r3 = atomicAdd(&g_deg[d3], 1);
        g_csp[(d0 << CAP_SHIFT) + r0] = s0;
        g_csp[(d1 << CAP_SHIFT) + r1] = s1;
        g_csp[(d2 << CAP_SHIFT) + r2] = s2;
        g_csp[(d3 << CAP_SHIFT) + r3] = s3;
    } else {
        for (int e = base; e < NUM_EDGES; e++) {
            int d = dst[e];
            int r = atomicAdd(&g_deg[d], 1);
            g_csp[(d << CAP_SHIFT) + r] = src[e];
        }
    }
}

// Prep: per-node scalars (dinv, sqd, deg copy), self-clean g_deg, and convert
// this block's 256 emb rows to fp16 y-space (coalesced float4 sweep).
__global__ void prep_kernel(const float4* __restrict__ emb4) {
    __shared__ float sdinv[256];
    int i = blockIdx.x * 256 + threadIdx.x;
    int v = 0;
    if (i < NUM_NODES) {
        v = g_deg[i];
        g_deg[i] = 0;                      // clean for next invocation
    }
    float dv = (v > 0) ? rsqrtf((float)v) : 0.0f;
    if (i < NUM_NODES) {
        g_dinv[i] = dv;
        g_sqd[i]  = (v > 0) ? sqrtf((float)v) : 0.0f;
        g_degc[i] = v;
    }
    sdinv[threadIdx.x] = dv;
    __syncthreads();

    // convert: 256 nodes * 16 float4 = 4096 float4 per block
    int nbase = blockIdx.x * 256;
    int fbase = nbase * 16;
    #pragma unroll
    for (int k = 0; k < 16; k++) {
        int idx  = k * 256 + threadIdx.x;
        int node = nbase + (idx >> 4);
        if (node < NUM_NODES) {
            float d = sdinv[idx >> 4];
            float4 val = __ldg(&emb4[fbase + idx]);
            __half2 lo = __floats2half2_rn(val.x * d, val.y * d);
            __half2 hi = __floats2half2_rn(val.z * d, val.w * d);
            uint2 p;
            p.x = *reinterpret_cast<unsigned*>(&lo);
            p.y = *reinterpret_cast<unsigned*>(&hi);
            reinterpret_cast<uint2*>(g_E)[fbase + idx] = p;
        }
    }
}

__device__ __forceinline__ float2 h2f(unsigned u) {
    __half2 h = *reinterpret_cast<__half2*>(&u);
    return __half22float2(h);
}

// Pull in y-space: sum = Σ_{s∈N(g)} y_in[s], bucket at [g*CAP, g*CAP+deg).
// 8 threads per dst node, one uint4 (8 halves) each — a warp's gather
// instruction covers 4 distinct 128B lines.
//   layer 0: E -> A:  y1 = sum / deg
//   layer 1: A -> B:  y2 = sum / deg
//   layer 2: out = (emb + sqrt(deg)*(y1+y2) + dinv*sum) * 0.25
__global__ void __launch_bounds__(256) pull_kernel(const float4* __restrict__ emb4,
                                                   float4* __restrict__ out4,
                                                   int layer) {
    int g = blockIdx.x * (blockDim.x >> 3) + (threadIdx.x >> 3);  // dst node
    int c = threadIdx.x & 7;                                      // uint4 lane
    if (g >= NUM_NODES) return;

    const uint4* xin;
    if (layer == 0)      xin = (const uint4*)g_E;
    else if (layer == 1) xin = (const uint4*)g_A;
    else                 xin = (const uint4*)g_B;

    int beg = g << CAP_SHIFT;
    int end = beg + __ldg(&g_degc[g]);

    float acc[8] = {0.f, 0.f, 0.f, 0.f, 0.f, 0.f, 0.f, 0.f};

    int e = beg;
    for (; e + 4 <= end; e += 4) {          // 4-way unroll for MLP vs L2 latency
        int s0 = __ldg(&g_csp[e]);
        int s1 = __ldg(&g_csp[e + 1]);
        int s2 = __ldg(&g_csp[e + 2]);
        int s3 = __ldg(&g_csp[e + 3]);
        uint4 v0 = __ldg(&xin[s0 * 8 + c]);
        uint4 v1 = __ldg(&xin[s1 * 8 + c]);
        uint4 v2 = __ldg(&xin[s2 * 8 + c]);
        uint4 v3 = __ldg(&xin[s3 * 8 + c]);
        float2 f;
        f = h2f(v0.x); acc[0] += f.x; acc[1] += f.y;
        f = h2f(v0.y); acc[2] += f.x; acc[3] += f.y;
        f = h2f(v0.z); acc[4] += f.x; acc[5] += f.y;
        f = h2f(v0.w); acc[6] += f.x; acc[7] += f.y;
        f = h2f(v1.x); acc[0] += f.x; acc[1] += f.y;
        f = h2f(v1.y); acc[2] += f.x; acc[3] += f.y;
        f = h2f(v1.z); acc[4] += f.x; acc[5] += f.y;
        f = h2f(v1.w); acc[6] += f.x; acc[7] += f.y;
        f = h2f(v2.x); acc[0] += f.x; acc[1] += f.y;
        f = h2f(v2.y); acc[2] += f.x; acc[3] += f.y;
        f = h2f(v2.z); acc[4] += f.x; acc[5] += f.y;
        f = h2f(v2.w); acc[6] += f.x; acc[7] += f.y;
        f = h2f(v3.x); acc[0] += f.x; acc[1] += f.y;
        f = h2f(v3.y); acc[2] += f.x; acc[3] += f.y;
        f = h2f(v3.z); acc[4] += f.x; acc[5] += f.y;
        f = h2f(v3.w); acc[6] += f.x; acc[7] += f.y;
    }
    for (; e < end; e++) {
        int s0 = __ldg(&g_csp[e]);
        uint4 v0 = __ldg(&xin[s0 * 8 + c]);
        float2 f;
        f = h2f(v0.x); acc[0] += f.x; acc[1] += f.y;
        f = h2f(v0.y); acc[2] += f.x; acc[3] += f.y;
        f = h2f(v0.z); acc[4] += f.x; acc[5] += f.y;
        f = h2f(v0.w); acc[6] += f.x; acc[7] += f.y;
    }

    if (layer < 2) {
        float dv = __ldg(&g_dinv[g]);
        float inv_deg = dv * dv;            // 1/deg (0 if deg==0)
        __half2 h0 = __floats2half2_rn(acc[0] * inv_deg, acc[1] * inv_deg);
        __half2 h1 = __floats2half2_rn(acc[2] * inv_deg, acc[3] * inv_deg);
        __half2 h2 = __floats2half2_rn(acc[4] * inv_deg, acc[5] * inv_deg);
        __half2 h3 = __floats2half2_rn(acc[6] * inv_deg, acc[7] * inv_deg);
        uint4 p;
        p.x = *reinterpret_cast<unsigned*>(&h0);
        p.y = *reinterpret_cast<unsigned*>(&h1);
        p.z = *reinterpret_cast<unsigned*>(&h2);
        p.w = *reinterpret_cast<unsigned*>(&h3);
        uint4* xout = (layer == 0) ? (uint4*)g_A : (uint4*)g_B;
        xout[g * 8 + c] = p;
    } else {
        float dv = __ldg(&g_dinv[g]);
        float sq = __ldg(&g_sqd[g]);        // sqrt(deg)
        uint4 ap = ((const uint4*)g_A)[g * 8 + c];
        uint4 bp = ((const uint4*)g_B)[g * 8 + c];
        float2 a0 = h2f(ap.x), a1 = h2f(ap.y), a2 = h2f(ap.z), a3 = h2f(ap.w);
        float2 b0 = h2f(bp.x), b1 = h2f(bp.y), b2 = h2f(bp.z), b3 = h2f(bp.w);
        int base = g * 16 + c * 2;          // float4 index into emb/out
        float4 e0 = __ldg(&emb4[base]);
        float4 e1 = __ldg(&emb4[base + 1]);
        float4 r0, r1;
        r0.x = (e0.x + sq * (a0.x + b0.x) + dv * acc[0]) * 0.25f;
        r0.y = (e0.y + sq * (a0.y + b0.y) + dv * acc[1]) * 0.25f;
        r0.z = (e0.z + sq * (a1.x + b1.x) + dv * acc[2]) * 0.25f;
        r0.w = (e0.w + sq * (a1.y + b1.y) + dv * acc[3]) * 0.25f;
        r1.x = (e1.x + sq * (a2.x + b2.x) + dv * acc[4]) * 0.25f;
        r1.y = (e1.y + sq * (a2.y + b2.y) + dv * acc[5]) * 0.25f;
        r1.z = (e1.z + sq * (a3.x + b3.x) + dv * acc[6]) * 0.25f;
        r1.w = (e1.w + sq * (a3.y + b3.y) + dv * acc[7]) * 0.25f;
        out4[base]     = r0;
        out4[base + 1] = r1;
    }
}

extern "C" void kernel_launch(void* const* d_in, const int* in_sizes, int n_in,
                              void* d_out, int out_size) {
    const int*   edge = (const int*)d_in[0];   // [2, NUM_EDGES]
    const float* emb  = (const float*)d_in[1]; // [NUM_NODES, EMB_DIM]
    const int* src = edge;
    const int* dst = edge + NUM_EDGES;
    const float4* emb4 = (const float4*)emb;
    float4* out4 = (float4*)d_out;

    const int TPB = 256;

    // g_deg is zero at module load and re-zeroed by prep_kernel each run.
    build_kernel<<<(NUM_EDGES / 4 + TPB - 1) / TPB, TPB>>>(src, dst);
    prep_kernel<<<(NUM_NODES + 255) / 256, 256>>>(emb4);

    const int nodes_per_block = TPB / 8;   // 32 nodes per block
    const int pull_blocks = (NUM_NODES + nodes_per_block - 1) / nodes_per_block;

    pull_kernel<<<pull_blocks, TPB>>>(emb4, out4, 0);  // E -> A
    pull_kernel<<<pull_blocks, TPB>>>(emb4, out4, 1);  // A -> B
    pull_kernel<<<pull_blocks, TPB>>>(emb4, out4, 2);  // B -> out (fused)
}

// round 12
// speedup vs baseline: 1.8550x; 1.0973x over previous
#include <cuda_runtime.h>
#include <cuda_fp16.h>

#define NUM_NODES 100000
#define EMB_DIM   64
#define NUM_EDGES 1280000
#define CAP       64        // per-node bucket capacity (P(overflow) ~ 3e-18)
#define CAP_SHIFT 6

// ---- scratch (static device globals; no allocation allowed) ----
// Propagated states stored as y = dinv * x, fp16: 8 uint4 (32 uints) per node row.
__device__ __align__(16) unsigned g_E[NUM_NODES * 32];  // y0 = dinv*emb
__device__ __align__(16) unsigned g_A[NUM_NODES * 32];  // y1
__device__ __align__(16) unsigned g_B[NUM_NODES * 32];  // y2
__device__ float g_dinv[NUM_NODES];      // deg^-1/2 (0 if deg==0)
__device__ float g_sqd[NUM_NODES];       // deg^+1/2 (0 if deg==0)
__device__ int   g_deg[NUM_NODES];       // zero at load; self-cleaned by prep
__device__ int   g_degc[NUM_NODES];      // stable copy for the pull kernels
__device__ int   g_csp[NUM_NODES * CAP]; // padded CSR: src per slot

// Single-pass CSR build: rank from the atomic, direct store into the padded
// bucket. 4 edges/thread so the 4 ATOMG returns overlap (MLP=4 vs 318 cyc).
__global__ void build_kernel(const int* __restrict__ src, const int* __restrict__ dst) {
    int base = (blockIdx.x * blockDim.x + threadIdx.x) * 4;
    if (base + 4 <= NUM_EDGES) {
        int d0 = __ldg(&dst[base]),     d1 = __ldg(&dst[base + 1]);
        int d2 = __ldg(&dst[base + 2]), d3 = __ldg(&dst[base + 3]);
        int s0 = __ldg(&src[base]),     s1 = __ldg(&src[base + 1]);
        int s2 = __ldg(&src[base + 2]), s3 = __ldg(&src[base + 3]);
        int r0 = atomicAdd(&g_deg[d0], 1);
        int r1 = atomicAdd(&g_deg[d1], 1);
        int r2 = atomicAdd(&g_deg[d2], 1);
        int r3 = atomicAdd(&g_deg[d3], 1);
        g_csp[(d0 << CAP_SHIFT) + r0] = s0;
        g_csp[(d1 << CAP_SHIFT) + r1] = s1;
        g_csp[(d2 << CAP_SHIFT) + r2] = s2;
        g_csp[(d3 << CAP_SHIFT) + r3] = s3;
    } else {
        for (int e = base; e < NUM_EDGES; e++) {
            int d = dst[e];
            int r = atomicAdd(&g_deg[d], 1);
            g_csp[(d << CAP_SHIFT) + r] = src[e];
        }
    }
}

// Prep: per-node scalars (dinv, sqd, deg copy), self-clean g_deg, and convert
// this block's 256 emb rows to fp16 y-space (coalesced float4 sweep).
__global__ void prep_kernel(const float4* __restrict__ emb4) {
    __shared__ float sdinv[256];
    int i = blockIdx.x * 256 + threadIdx.x;
    int v = 0;
    if (i < NUM_NODES) {
        v = g_deg[i];
        g_deg[i] = 0;                      // clean for next invocation
    }
    float dv = (v > 0) ? rsqrtf((float)v) : 0.0f;
    if (i < NUM_NODES) {
        g_dinv[i] = dv;
        g_sqd[i]  = (v > 0) ? sqrtf((float)v) : 0.0f;
        g_degc[i] = v;
    }
    sdinv[threadIdx.x] = dv;
    __syncthreads();

    int nbase = blockIdx.x * 256;
    int fbase = nbase * 16;
    #pragma unroll
    for (int k = 0; k < 16; k++) {
        int idx  = k * 256 + threadIdx.x;
        int node = nbase + (idx >> 4);
        if (node < NUM_NODES) {
            float d = sdinv[idx >> 4];
            float4 val = __ldg(&emb4[fbase + idx]);
            __half2 lo = __floats2half2_rn(val.x * d, val.y * d);
            __half2 hi = __floats2half2_rn(val.z * d, val.w * d);
            uint2 p;
            p.x = *reinterpret_cast<unsigned*>(&lo);
            p.y = *reinterpret_cast<unsigned*>(&hi);
            reinterpret_cast<uint2*>(g_E)[fbase + idx] = p;
        }
    }
}

__device__ __forceinline__ float2 h2f(unsigned u) {
    __half2 h = *reinterpret_cast<__half2*>(&u);
    return __half22float2(h);
}

__device__ __forceinline__ unsigned uadd2(unsigned a, unsigned b) {
    __half2 r = __hadd2(*reinterpret_cast<__half2*>(&a),
                        *reinterpret_cast<__half2*>(&b));
    return *reinterpret_cast<unsigned*>(&r);
}

// Pull in y-space: sum = Σ_{s∈N(g)} y_in[s], bucket at [g*CAP, g*CAP+deg).
// 8 threads per dst node, one uint4 (8 halves) each — a warp's gather
// instruction covers 4 distinct 128B lines.
// Inner loop: 4 gathered rows tree-reduced in fp16 (depth 2, HADD2), then
// converted once to fp32 and accumulated — ~2x less math than per-row convert.
//   layer 0: E -> A:  y1 = sum / deg
//   layer 1: A -> B:  y2 = sum / deg
//   layer 2: out = (emb + sqrt(deg)*(y1+y2) + dinv*sum) * 0.25
__global__ void __launch_bounds__(256) pull_kernel(const float4* __restrict__ emb4,
                                                   float4* __restrict__ out4,
                                                   int layer) {
    int g = blockIdx.x * (blockDim.x >> 3) + (threadIdx.x >> 3);  // dst node
    int c = threadIdx.x & 7;                                      // uint4 lane
    if (g >= NUM_NODES) return;

    const uint4* xin;
    if (layer == 0)      xin = (const uint4*)g_E;
    else if (layer == 1) xin = (const uint4*)g_A;
    else                 xin = (const uint4*)g_B;

    int beg = g << CAP_SHIFT;
    int end = beg + __ldg(&g_degc[g]);

    float acc[8] = {0.f, 0.f, 0.f, 0.f, 0.f, 0.f, 0.f, 0.f};

    int e = beg;
    for (; e + 4 <= end; e += 4) {
        int s0 = __ldg(&g_csp[e]);
        int s1 = __ldg(&g_csp[e + 1]);
        int s2 = __ldg(&g_csp[e + 2]);
        int s3 = __ldg(&g_csp[e + 3]);
        uint4 v0 = __ldg(&xin[s0 * 8 + c]);
        uint4 v1 = __ldg(&xin[s1 * 8 + c]);
        uint4 v2 = __ldg(&xin[s2 * 8 + c]);
        uint4 v3 = __ldg(&xin[s3 * 8 + c]);
        // fp16 tree reduction (depth 2), then one fp32 accumulate
        unsigned sx = uadd2(uadd2(v0.x, v1.x), uadd2(v2.x, v3.x));
        unsigned sy = uadd2(uadd2(v0.y, v1.y), uadd2(v2.y, v3.y));
        unsigned sz = uadd2(uadd2(v0.z, v1.z), uadd2(v2.z, v3.z));
        unsigned sw = uadd2(uadd2(v0.w, v1.w), uadd2(v2.w, v3.w));
        float2 f;
        f = h2f(sx); acc[0] += f.x; acc[1] += f.y;
        f = h2f(sy); acc[2] += f.x; acc[3] += f.y;
        f = h2f(sz); acc[4] += f.x; acc[5] += f.y;
        f = h2f(sw); acc[6] += f.x; acc[7] += f.y;
    }
    if (e + 2 <= end) {                      // 2-edge remainder: depth-1 tree
        int s0 = __ldg(&g_csp[e]);
        int s1 = __ldg(&g_csp[e + 1]);
        uint4 v0 = __ldg(&xin[s0 * 8 + c]);
        uint4 v1 = __ldg(&xin[s1 * 8 + c]);
        unsigned sx = uadd2(v0.x, v1.x);
        unsigned sy = uadd2(v0.y, v1.y);
        unsigned sz = uadd2(v0.z, v1.z);
        unsigned sw = uadd2(v0.w, v1.w);
        float2 f;
        f = h2f(sx); acc[0] += f.x; acc[1] += f.y;
        f = h2f(sy); acc[2] += f.x; acc[3] += f.y;
        f = h2f(sz); acc[4] += f.x; acc[5] += f.y;
        f = h2f(sw); acc[6] += f.x; acc[7] += f.y;
        e += 2;
    }
    if (e < end) {                           // 1-edge remainder
        int s0 = __ldg(&g_csp[e]);
        uint4 v0 = __ldg(&xin[s0 * 8 + c]);
        float2 f;
        f = h2f(v0.x); acc[0] += f.x; acc[1] += f.y;
        f = h2f(v0.y); acc[2] += f.x; acc[3] += f.y;
        f = h2f(v0.z); acc[4] += f.x; acc[5] += f.y;
        f = h2f(v0.w); acc[6] += f.x; acc[7] += f.y;
    }

    if (layer < 2) {
        float dv = __ldg(&g_dinv[g]);
        float inv_deg = dv * dv;            // 1/deg (0 if deg==0)
        __half2 h0 = __floats2half2_rn(acc[0] * inv_deg, acc[1] * inv_deg);
        __half2 h1 = __floats2half2_rn(acc[2] * inv_deg, acc[3] * inv_deg);
        __half2 h2 = __floats2half2_rn(acc[4] * inv_deg, acc[5] * inv_deg);
        __half2 h3 = __floats2half2_rn(acc[6] * inv_deg, acc[7] * inv_deg);
        uint4 p;
        p.x = *reinterpret_cast<unsigned*>(&h0);
        p.y = *reinterpret_cast<unsigned*>(&h1);
        p.z = *reinterpret_cast<unsigned*>(&h2);
        p.w = *reinterpret_cast<unsigned*>(&h3);
        uint4* xout = (layer == 0) ? (uint4*)g_A : (uint4*)g_B;
        xout[g * 8 + c] = p;
    } else {
        float dv = __ldg(&g_dinv[g]);
        float sq = __ldg(&g_sqd[g]);        // sqrt(deg)
        uint4 ap = ((const uint4*)g_A)[g * 8 + c];
        uint4 bp = ((const uint4*)g_B)[g * 8 + c];
        float2 a0 = h2f(ap.x), a1 = h2f(ap.y), a2 = h2f(ap.z), a3 = h2f(ap.w);
        float2 b0 = h2f(bp.x), b1 = h2f(bp.y), b2 = h2f(bp.z), b3 = h2f(bp.w);
        int base = g * 16 + c * 2;          // float4 index into emb/out
        float4 e0 = __ldg(&emb4[base]);
        float4 e1 = __ldg(&emb4[base + 1]);
        float4 r0, r1;
        r0.x = (e0.x + sq * (a0.x + b0.x) + dv * acc[0]) * 0.25f;
        r0.y = (e0.y + sq * (a0.y + b0.y) + dv * acc[1]) * 0.25f;
        r0.z = (e0.z + sq * (a1.x + b1.x) + dv * acc[2]) * 0.25f;
        r0.w = (e0.w + sq * (a1.y + b1.y) + dv * acc[3]) * 0.25f;
        r1.x = (e1.x + sq * (a2.x + b2.x) + dv * acc[4]) * 0.25f;
        r1.y = (e1.y + sq * (a2.y + b2.y) + dv * acc[5]) * 0.25f;
        r1.z = (e1.z + sq * (a3.x + b3.x) + dv * acc[6]) * 0.25f;
        r1.w = (e1.w + sq * (a3.y + b3.y) + dv * acc[7]) * 0.25f;
        out4[base]     = r0;
        out4[base + 1] = r1;
    }
}

extern "C" void kernel_launch(void* const* d_in, const int* in_sizes, int n_in,
                              void* d_out, int out_size) {
    const int*   edge = (const int*)d_in[0];   // [2, NUM_EDGES]
    const float* emb  = (const float*)d_in[1]; // [NUM_NODES, EMB_DIM]
    const int* src = edge;
    const int* dst = edge + NUM_EDGES;
    const float4* emb4 = (const float4*)emb;
    float4* out4 = (float4*)d_out;

    const int TPB = 256;

    // g_deg is zero at module load and re-zeroed by prep_kernel each run.
    build_kernel<<<(NUM_EDGES / 4 + TPB - 1) / TPB, TPB>>>(src, dst);
    prep_kernel<<<(NUM_NODES + 255) / 256, 256>>>(emb4);

    const int nodes_per_block = TPB / 8;   // 32 nodes per block
    const int pull_blocks = (NUM_NODES + nodes_per_block - 1) / nodes_per_block;

    pull_kernel<<<pull_blocks, TPB>>>(emb4, out4, 0);  // E -> A
    pull_kernel<<<pull_blocks, TPB>>>(emb4, out4, 1);  // A -> B
    pull_kernel<<<pull_blocks, TPB>>>(emb4, out4, 2);  // B -> out (fused)
}